// round 1
// baseline (speedup 1.0000x reference)
#include <cuda_runtime.h>
#include <cstdint>

// Problem constants (CenterLoss: BATCH=4096, FEAT_DIM=256, NUM_CLASSES=8192)
#define BATCH       4096
#define FEAT_DIM    256
#define NUM_CLASSES 8192

// Scratch: per-sample squared distances (no device allocation allowed)
__device__ float g_partial[BATCH];
// Label dtype flag: 1 -> int64 layout, 0 -> int32 layout
__device__ int g_labels_are_i64;

// ---------------------------------------------------------------------------
// Probe label dtype. If labels are int64 (little-endian), every odd 32-bit
// word is 0 (labels < 8192). If int32, odd words are uniform labels in
// [0, 8192); probability all 64 probed words are zero is 8192^-64 ~ 0.
// ---------------------------------------------------------------------------
__global__ void detect_label_dtype(const int* __restrict__ labels32) {
    // 64 threads probe words 1, 3, 5, ..., 127 (all within 4096 int32s).
    int w = labels32[2 * threadIdx.x + 1];
    unsigned any = __ballot_sync(0xFFFFFFFFu, w != 0);
    // reduce across the 2 warps via shared
    __shared__ unsigned s_any[2];
    if ((threadIdx.x & 31) == 0) s_any[threadIdx.x >> 5] = any;
    __syncthreads();
    if (threadIdx.x == 0) {
        g_labels_are_i64 = (s_any[0] | s_any[1]) ? 0 : 1;
    }
}

// ---------------------------------------------------------------------------
// Warp per sample: d_b = ||x_b - centers[label_b]||^2
// FEAT_DIM=256 -> 64 float4 per row -> 2 float4 per lane.
// ---------------------------------------------------------------------------
__global__ void __launch_bounds__(256) per_sample_dist(
    const float* __restrict__ x,
    const void*  __restrict__ labels_raw,
    const float* __restrict__ centers)
{
    int gwarp = (blockIdx.x * blockDim.x + threadIdx.x) >> 5;
    int lane  = threadIdx.x & 31;
    if (gwarp >= BATCH) return;

    long long lbl;
    if (g_labels_are_i64) {
        lbl = ((const long long*)labels_raw)[gwarp];
    } else {
        lbl = (long long)(((const int*)labels_raw)[gwarp]);
    }

    const float4* xr = (const float4*)(x + (size_t)gwarp * FEAT_DIM);
    const float4* cr = (const float4*)(centers + (size_t)lbl * FEAT_DIM);

    float acc = 0.0f;
#pragma unroll
    for (int i = 0; i < 2; i++) {
        float4 a = xr[lane + 32 * i];
        float4 c = cr[lane + 32 * i];
        float d0 = a.x - c.x;
        float d1 = a.y - c.y;
        float d2 = a.z - c.z;
        float d3 = a.w - c.w;
        acc = fmaf(d0, d0, acc);
        acc = fmaf(d1, d1, acc);
        acc = fmaf(d2, d2, acc);
        acc = fmaf(d3, d3, acc);
    }
#pragma unroll
    for (int o = 16; o > 0; o >>= 1)
        acc += __shfl_xor_sync(0xFFFFFFFFu, acc, o);
    if (lane == 0) g_partial[gwarp] = acc;
}

// ---------------------------------------------------------------------------
// Deterministic single-block reduction of the 4096 partials.
// loss = sum(clip(d_b, 1e-12, 1e12)) / B + (C-1)*1e-12
// ---------------------------------------------------------------------------
__global__ void __launch_bounds__(256) final_reduce(float* __restrict__ out)
{
    __shared__ float s[256];
    float acc = 0.0f;
    for (int i = threadIdx.x; i < BATCH; i += 256) {
        float v = g_partial[i];
        v = fminf(fmaxf(v, 1e-12f), 1e12f);
        acc += v;
    }
    s[threadIdx.x] = acc;
    __syncthreads();
#pragma unroll
    for (int o = 128; o > 0; o >>= 1) {
        if (threadIdx.x < o) s[threadIdx.x] += s[threadIdx.x + o];
        __syncthreads();
    }
    if (threadIdx.x == 0) {
        out[0] = s[0] / (float)BATCH
               + (float)(NUM_CLASSES - 1) * 1e-12f;
    }
}

extern "C" void kernel_launch(void* const* d_in, const int* in_sizes, int n_in,
                              void* d_out, int out_size)
{
    const float* x       = (const float*)d_in[0];
    const void*  labels  = d_in[1];
    const float* centers = (const float*)d_in[2];
    float*       out     = (float*)d_out;
    (void)in_sizes; (void)n_in; (void)out_size;

    detect_label_dtype<<<1, 64>>>((const int*)labels);
    // 4096 warps, 8 warps per block -> 512 blocks
    per_sample_dist<<<BATCH / 8, 256>>>(x, labels, centers);
    final_reduce<<<1, 256>>>(out);
}

// round 2
// speedup vs baseline: 1.4353x; 1.4353x over previous
#include <cuda_runtime.h>
#include <cstdint>

// CenterLoss: BATCH=4096, FEAT_DIM=256, NUM_CLASSES=8192
#define BATCH       4096
#define FEAT_DIM    256
#define NUM_CLASSES 8192
#define NBLOCKS     512          // 8 warps/block, warp-per-sample
#define SCALE       268435456.0  // 2^28 fixed-point scale

// Persistent scratch (reset by the last block each launch, so graph replays
// always start from zero).
__device__ unsigned long long g_sum   = 0ull;
__device__ unsigned int       g_count = 0u;

// ---------------------------------------------------------------------------
// Single fused kernel:
//   - per-warp label-dtype probe (sync-free, identical data in every warp)
//   - warp-per-sample ||x_b - centers[label_b]||^2
//   - clamp, fixed-point convert, block reduce, one u64 atomic per block
//   - last block finalizes output and resets scratch
// ---------------------------------------------------------------------------
__global__ void __launch_bounds__(256) center_loss_fused(
    const float* __restrict__ x,
    const void*  __restrict__ labels_raw,
    const float* __restrict__ centers,
    float*       __restrict__ out)
{
    const int lane  = threadIdx.x & 31;
    const int warp  = threadIdx.x >> 5;            // 0..7
    const int gwarp = blockIdx.x * 8 + warp;       // sample id, 0..4095

    // ---- dtype probe: odd 32-bit words 1,3,...,15 (in-bounds for both
    // int32 [4096 words] and int64 [8192 words] layouts). If labels are
    // int64 little-endian, all hi words are 0 (labels < 8192). If int32,
    // these are 8 labels; all-zero has probability 8192^-8.
    const int* labels32 = (const int*)labels_raw;
    int probe = (lane < 8) ? labels32[2 * lane + 1] : 0;
    unsigned ball = __ballot_sync(0xFFFFFFFFu, probe != 0);
    const bool labels_i64 = (ball == 0);

    long long lbl;
    if (labels_i64) lbl = ((const long long*)labels_raw)[gwarp];
    else            lbl = (long long)labels32[gwarp];

    // ---- squared distance: 256 floats = 64 float4 = 2 float4 per lane
    const float4* xr = (const float4*)(x + (size_t)gwarp * FEAT_DIM);
    const float4* cr = (const float4*)(centers + (size_t)lbl * FEAT_DIM);

    float4 a0 = xr[lane];
    float4 c0 = cr[lane];
    float4 a1 = xr[lane + 32];
    float4 c1 = cr[lane + 32];

    float acc = 0.0f;
    float d;
    d = a0.x - c0.x; acc = fmaf(d, d, acc);
    d = a0.y - c0.y; acc = fmaf(d, d, acc);
    d = a0.z - c0.z; acc = fmaf(d, d, acc);
    d = a0.w - c0.w; acc = fmaf(d, d, acc);
    d = a1.x - c1.x; acc = fmaf(d, d, acc);
    d = a1.y - c1.y; acc = fmaf(d, d, acc);
    d = a1.z - c1.z; acc = fmaf(d, d, acc);
    d = a1.w - c1.w; acc = fmaf(d, d, acc);

#pragma unroll
    for (int o = 16; o > 0; o >>= 1)
        acc += __shfl_xor_sync(0xFFFFFFFFu, acc, o);

    // ---- block reduce in fixed point (deterministic) ----
    __shared__ unsigned long long s[8];
    if (lane == 0) {
        float v = fminf(fmaxf(acc, 1e-12f), 1e12f);
        s[warp] = (unsigned long long)((double)v * SCALE);
    }
    __syncthreads();

    if (threadIdx.x == 0) {
        unsigned long long bsum = 0ull;
#pragma unroll
        for (int i = 0; i < 8; i++) bsum += s[i];
        atomicAdd(&g_sum, bsum);
        __threadfence();
        unsigned int old = atomicAdd(&g_count, 1u);
        if (old == NBLOCKS - 1) {
            unsigned long long total = atomicAdd(&g_sum, 0ull);  // ordered read
            double loss = ((double)total / SCALE) / (double)BATCH
                        + (double)(NUM_CLASSES - 1) * 1e-12;
            out[0] = (float)loss;
            // reset scratch for the next graph replay
            g_sum   = 0ull;
            g_count = 0u;
        }
    }
}

extern "C" void kernel_launch(void* const* d_in, const int* in_sizes, int n_in,
                              void* d_out, int out_size)
{
    const float* x       = (const float*)d_in[0];
    const void*  labels  = d_in[1];
    const float* centers = (const float*)d_in[2];
    float*       out     = (float*)d_out;
    (void)in_sizes; (void)n_in; (void)out_size;

    center_loss_fused<<<NBLOCKS, 256>>>(x, labels, centers, out);
}